// round 1
// baseline (speedup 1.0000x reference)
#include <cuda_runtime.h>
#include <float.h>

#define NPTS   65536
#define BGRAPH 64
#define PPG    1024

// ---------------- scratch (device globals; no allocation) ----------------
__device__ int   g_knn[NPTS * 8];     // top-6 neighbor indices (sorted by d2), padded to 8
__device__ float g_ab [NPTS * 128];   // per-point a (cols 0..63) and b (cols 64..127)
__device__ float g_h1 [NPTS * 64];
__device__ float g_h2 [NPTS * 64];

// ---------------- kNN (k=6, matches jax top_k(-d2, 6) incl. ties) ----------------
__global__ __launch_bounds__(256) void knn_kernel(const float* __restrict__ pos)
{
    __shared__ float4 cand[256];
    int graph = blockIdx.x >> 2;
    int q = graph * PPG + ((blockIdx.x & 3) << 8) + threadIdx.x;
    float qx = pos[3*q], qy = pos[3*q+1], qz = pos[3*q+2];
    float qs = qx*qx + qy*qy + qz*qz;
    float bd[6]; int bi[6];
#pragma unroll
    for (int t = 0; t < 6; t++) { bd[t] = FLT_MAX; bi[t] = 0; }
    for (int tile = 0; tile < PPG; tile += 256) {
        int c = graph * PPG + tile + threadIdx.x;
        float cx = pos[3*c], cy = pos[3*c+1], cz = pos[3*c+2];
        cand[threadIdx.x] = make_float4(cx, cy, cz, cx*cx + cy*cy + cz*cz);
        __syncthreads();
#pragma unroll 4
        for (int u = 0; u < 256; u++) {
            float4 p = cand[u];
            float d2 = qs + p.w - 2.0f*(qx*p.x + qy*p.y + qz*p.z);
            if (d2 < bd[5]) {               // strict <: equal-dist later index not inserted
                bd[5] = d2; bi[5] = graph*PPG + tile + u;
#pragma unroll
                for (int t = 5; t > 0; t--) {
                    if (bd[t] < bd[t-1]) {  // strict <: stable for ties (lower idx first)
                        float td = bd[t]; bd[t] = bd[t-1]; bd[t-1] = td;
                        int   ti = bi[t]; bi[t] = bi[t-1]; bi[t-1] = ti;
                    }
                }
            }
        }
        __syncthreads();
    }
#pragma unroll
    for (int t = 0; t < 6; t++) g_knn[q*8 + t] = bi[t];
}

// ---------------- per-point a/b projections, layer 1 (Cin=3) ----------------
__global__ __launch_bounds__(256) void ab3_kernel(const float* __restrict__ pos,
                                                  const float* __restrict__ W1)
{
    int idx = blockIdx.x * 256 + threadIdx.x;   // NPTS*64 threads
    int i = idx >> 6, c = idx & 63;
    float x = pos[3*i], y = pos[3*i+1], z = pos[3*i+2];
    g_ab[i*128 + c]      = x*W1[c]       + y*W1[64  + c] + z*W1[128 + c];
    g_ab[i*128 + 64 + c] = x*W1[192 + c] + y*W1[256 + c] + z*W1[320 + c];
}

// ---------------- per-point a/b projections, layers 2/3 (Cin=64) ----------------
// ab[i][cc] = sum_f h[i][f] * WW[f][cc],  WW[f][cc<64]=W1[f][cc], WW[f][cc>=64]=W1[64+f][cc-64]
#define AB64_SMEM ((64*65 + 64*128) * 4)
__global__ __launch_bounds__(256) void ab64_kernel(const float* __restrict__ h,
                                                   const float* __restrict__ W1)
{
    extern __shared__ float smem[];
    float* hs = smem;            // [64][65] point-major, padded (bank-conflict-free)
    float* Ws = smem + 64*65;    // [64][128]
    int tx = threadIdx.x;
    int base = blockIdx.x * 64;
    for (int t = tx; t < 4096; t += 256) hs[(t>>6)*65 + (t&63)] = h[base*64 + t];
    for (int t = tx; t < 8192; t += 256) {
        int f = t >> 7, cc = t & 127;
        Ws[t] = (cc < 64) ? W1[f*64 + cc] : W1[(64 + f)*64 + (cc - 64)];
    }
    __syncthreads();
    int p0 = (tx & 7) * 8;        // 8 points per thread
    int c0 = (tx >> 3) * 4;       // 4 output cols per thread
    float acc[8][4];
#pragma unroll
    for (int i = 0; i < 8; i++)
#pragma unroll
        for (int j = 0; j < 4; j++) acc[i][j] = 0.f;
#pragma unroll 4
    for (int kk = 0; kk < 64; kk++) {
        float4 w = *(const float4*)&Ws[kk*128 + c0];
#pragma unroll
        for (int i = 0; i < 8; i++) {
            float hv = hs[(p0 + i)*65 + kk];
            acc[i][0] = fmaf(hv, w.x, acc[i][0]);
            acc[i][1] = fmaf(hv, w.y, acc[i][1]);
            acc[i][2] = fmaf(hv, w.z, acc[i][2]);
            acc[i][3] = fmaf(hv, w.w, acc[i][3]);
        }
    }
#pragma unroll
    for (int i = 0; i < 8; i++) {
        float4 o = make_float4(acc[i][0], acc[i][1], acc[i][2], acc[i][3]);
        *(float4*)&g_ab[(size_t)(base + p0 + i)*128 + c0] = o;
    }
}

// ---------------- edge kernel: hidden + W2 GEMM + max over k + relu ----------------
// warp per point; lane owns output channels (lane, lane+32); W2 columns cached in registers.
template<int K>
__global__ __launch_bounds__(128, 2) void edge_kernel(
    const float* __restrict__ pos,
    const float* __restrict__ W1rel,   // rows [2*Cin .. 2*Cin+2] of W1, i.e. [3][64]
    const float* __restrict__ b1,
    const float* __restrict__ W2,      // [64][64]
    const float* __restrict__ b2,
    float* __restrict__ hout,
    int ppw)
{
    __shared__ __align__(16) float hid[4][K][64];
    int lane = threadIdx.x & 31, warp = threadIdx.x >> 5;
    int c0 = lane, c1 = lane + 32;
    float w20[64], w21[64];
#pragma unroll
    for (int h = 0; h < 64; h++) { w20[h] = W2[h*64 + c0]; w21[h] = W2[h*64 + c1]; }
    float wr00 = W1rel[c0],       wr01 = W1rel[c1];
    float wr10 = W1rel[64  + c0], wr11 = W1rel[64  + c1];
    float wr20 = W1rel[128 + c0], wr21 = W1rel[128 + c1];
    float b1c0 = b1[c0], b1c1 = b1[c1];
    float b2c0 = b2[c0], b2c1 = b2[c1];
    float (*myhid)[64] = hid[warp];
    int pbase = (blockIdx.x * 4 + warp) * ppw;

    for (int pp = 0; pp < ppw; pp++) {
        int i = pbase + pp;
        float a0 = g_ab[i*128 + c0], a1 = g_ab[i*128 + c1];
        float pix = pos[3*i], piy = pos[3*i+1], piz = pos[3*i+2];
        // phase A: all K hiddens (independent global loads -> good MLP)
#pragma unroll
        for (int e = 0; e < K; e++) {
            int j = g_knn[i*8 + e];
            float bb0 = g_ab[j*128 + 64 + c0];
            float bb1 = g_ab[j*128 + 64 + c1];
            float rx = pos[3*j]   - pix;
            float ry = pos[3*j+1] - piy;
            float rz = pos[3*j+2] - piz;
            float h0 = a0 + bb0 + b1c0;
            h0 = fmaf(rx, wr00, h0); h0 = fmaf(ry, wr10, h0); h0 = fmaf(rz, wr20, h0);
            float h1 = a1 + bb1 + b1c1;
            h1 = fmaf(rx, wr01, h1); h1 = fmaf(ry, wr11, h1); h1 = fmaf(rz, wr21, h1);
            myhid[e][c0] = fmaxf(h0, 0.f);
            myhid[e][c1] = fmaxf(h1, 0.f);
        }
        __syncwarp();
        // phase B: out = hidden @ W2, max over K (W2 in regs, hidden via LDS.128 broadcast)
        float m0 = -FLT_MAX, m1 = -FLT_MAX;
#pragma unroll
        for (int e = 0; e < K; e++) {
            float s0 = 0.f, s1 = 0.f;
#pragma unroll
            for (int hh = 0; hh < 16; hh++) {
                float4 v = *(const float4*)&myhid[e][4*hh];
                s0 = fmaf(w20[4*hh+0], v.x, s0); s1 = fmaf(w21[4*hh+0], v.x, s1);
                s0 = fmaf(w20[4*hh+1], v.y, s0); s1 = fmaf(w21[4*hh+1], v.y, s1);
                s0 = fmaf(w20[4*hh+2], v.z, s0); s1 = fmaf(w21[4*hh+2], v.z, s1);
                s0 = fmaf(w20[4*hh+3], v.w, s0); s1 = fmaf(w21[4*hh+3], v.w, s1);
            }
            m0 = fmaxf(m0, s0); m1 = fmaxf(m1, s1);
        }
        hout[i*64 + c0] = fmaxf(m0 + b2c0, 0.f);
        hout[i*64 + c1] = fmaxf(m1 + b2c1, 0.f);
        __syncwarp();
    }
}

// ---------------- global max pool + regression head ----------------
__global__ __launch_bounds__(256) void pool_kernel(const float* __restrict__ h,
                                                   const float* __restrict__ regW,
                                                   const float* __restrict__ regb,
                                                   float* __restrict__ out)
{
    __shared__ float red[4][64];
    int g = blockIdx.x;
    int c = threadIdx.x & 63, s = threadIdx.x >> 6;
    const float* hb = h + (size_t)g * PPG * 64;
    float m = -FLT_MAX;
    for (int p = s; p < PPG; p += 4) m = fmaxf(m, hb[p*64 + c]);
    red[s][c] = m;
    __syncthreads();
    if (threadIdx.x < 64)
        red[0][c] = fmaxf(fmaxf(red[0][c], red[1][c]), fmaxf(red[2][c], red[3][c]));
    __syncthreads();
    if (threadIdx.x < 6) {
        float acc = regb[threadIdx.x];
#pragma unroll
        for (int cc = 0; cc < 64; cc++)
            acc = fmaf(red[0][cc], regW[cc*6 + threadIdx.x], acc);
        out[g*6 + threadIdx.x] = acc;
    }
}

// ---------------- launch ----------------
extern "C" void kernel_launch(void* const* d_in, const int* in_sizes, int n_in,
                              void* d_out, int out_size)
{
    (void)in_sizes; (void)n_in; (void)out_size;
    const float* pos  = (const float*)d_in[1];   // d_in[0] = x (unused), d_in[2] = batch (unused)
    const float* c1W1 = (const float*)d_in[3];
    const float* c1b1 = (const float*)d_in[4];
    const float* c1W2 = (const float*)d_in[5];
    const float* c1b2 = (const float*)d_in[6];
    const float* c2W1 = (const float*)d_in[7];
    const float* c2b1 = (const float*)d_in[8];
    const float* c2W2 = (const float*)d_in[9];
    const float* c2b2 = (const float*)d_in[10];
    const float* c3W1 = (const float*)d_in[11];
    const float* c3b1 = (const float*)d_in[12];
    const float* c3W2 = (const float*)d_in[13];
    const float* c3b2 = (const float*)d_in[14];
    const float* regW = (const float*)d_in[15];
    const float* regb = (const float*)d_in[16];
    float* out = (float*)d_out;

    float *h1, *h2;
    cudaGetSymbolAddress((void**)&h1, g_h1);
    cudaGetSymbolAddress((void**)&h2, g_h2);
    cudaFuncSetAttribute(ab64_kernel, cudaFuncAttributeMaxDynamicSharedMemorySize, AB64_SMEM);

    const int PPW = 16;
    const int EDGE_GRID = NPTS / (4 * PPW);   // 1024 blocks of 128 threads

    knn_kernel<<<BGRAPH * 4, 256>>>(pos);
    ab3_kernel<<<NPTS * 64 / 256, 256>>>(pos, c1W1);
    edge_kernel<6><<<EDGE_GRID, 128>>>(pos, c1W1 + 6*64,   c1b1, c1W2, c1b2, h1, PPW);
    ab64_kernel<<<NPTS / 64, 256, AB64_SMEM>>>(h1, c2W1);
    edge_kernel<4><<<EDGE_GRID, 128>>>(pos, c2W1 + 128*64, c2b1, c2W2, c2b2, h2, PPW);
    ab64_kernel<<<NPTS / 64, 256, AB64_SMEM>>>(h2, c3W1);
    edge_kernel<3><<<EDGE_GRID, 128>>>(pos, c3W1 + 128*64, c3b1, c3W2, c3b2, h1, PPW);
    pool_kernel<<<BGRAPH, 256>>>(h1, regW, regb, out);
}